// round 7
// baseline (speedup 1.0000x reference)
#include <cuda_runtime.h>
#include <math.h>

// x [L=4096, B=4, D=1024] fp32, channel-contiguous (BD = 4096 floats/timestep)
#define L      4096
#define B      4
#define D      1024
#define BD     (B * D)      // 4096 channels
#define T      256          // output timesteps per CTA
#define W      512          // warmup history (gamma^512 <= ~6e-9 worst channel)
#define NCHUNK (L / T)      // 16
#define CBLK   128          // channels per CTA
#define NCB    (BD / CBLK)  // 32
#define UNR    16

// ---------------------------------------------------------------------------
// Single kernel: each CTA owns (chunk, channel-block). State entering the
// chunk is reconstructed by scanning the previous W steps from zero (exact
// for chunks whose window reaches t=0, where the true seed is applied).
// No inter-CTA communication of any kind.
// ---------------------------------------------------------------------------
__global__ void __launch_bounds__(CBLK)
spiral_scan(const float* __restrict__ x,
            const float* __restrict__ lmlg,
            const float* __restrict__ theta,
            const float* __restrict__ lci,
            float* __restrict__ out) {
    int bid   = blockIdx.x;
    int chunk = bid >> 5;            // / NCB
    int cb    = bid & (NCB - 1);
    int ch    = cb * CBLK + threadIdx.x;   // global channel 0..4095
    int d     = ch & (D - 1);

    // per-channel coefficient c = exp(-exp(lmlg)) * e^{i theta} (double prec)
    double g  = exp(-exp((double)lmlg[d]));
    double th = (double)theta[d];
    float cr = (float)(g * cos(th));
    float ci = (float)(g * sin(th));

    int start = chunk * T;
    int t0    = start - W;
    float sr, si = 0.f;
    if (t0 <= 0) { t0 = 0; sr = lci[d]; }   // exact seed when window hits t=0
    else         { sr = 0.f; }              // truncated history (error ~1e-8)

    // ---- warmup: scan [t0, start), no stores ----
    const float* xp = x + (size_t)t0 * BD + ch;
    int nwarm = start - t0;                  // multiple of UNR (0,256,512)
    for (int n = 0; n < nwarm; n += UNR) {
        float xv[UNR];
#pragma unroll
        for (int k = 0; k < UNR; k++)
            xv[k] = __ldg(xp + (size_t)(n + k) * BD);
#pragma unroll
        for (int k = 0; k < UNR; k++) {
            float nr = fmaf(cr, sr, fmaf(-ci, si, xv[k]));
            float ni = fmaf(ci, sr, cr * si);
            sr = nr; si = ni;
        }
    }

    // ---- main: scan [start, start+T), out = Re(s) * x, streaming stores ----
    const float* xm = x   + (size_t)start * BD + ch;
    float*       om = out + (size_t)start * BD + ch;
    for (int n = 0; n < T; n += UNR) {
        float xv[UNR];
#pragma unroll
        for (int k = 0; k < UNR; k++)
            xv[k] = __ldg(xm + (size_t)(n + k) * BD);
#pragma unroll
        for (int k = 0; k < UNR; k++) {
            float nr = fmaf(cr, sr, fmaf(-ci, si, xv[k]));
            float ni = fmaf(ci, sr, cr * si);
            sr = nr; si = ni;
            __stcs(om + (size_t)(n + k) * BD, nr * xv[k]);
        }
    }
}

// ---------------------------------------------------------------------------
extern "C" void kernel_launch(void* const* d_in, const int* in_sizes, int n_in,
                              void* d_out, int out_size) {
    const float* x    = (const float*)d_in[0];  // [L,B,D]
    const float* lmlg = (const float*)d_in[1];  // [D]
    const float* th   = (const float*)d_in[2];  // [D]
    const float* lci  = (const float*)d_in[3];  // [D]
    float* out = (float*)d_out;

    spiral_scan<<<NCHUNK * NCB, CBLK>>>(x, lmlg, th, lci, out);
}

// round 8
// speedup vs baseline: 3.0705x; 3.0705x over previous
#include <cuda_runtime.h>
#include <math.h>

// x [L=4096, B=4, D=1024] fp32, channel-contiguous (BD = 4096 per timestep)
#define L   4096
#define B   4
#define D   1024
#define BD  (B * D)        // 4096 channels
#define C   32             // time chunks
#define LC  (L / C)        // 128 steps per chunk
#define UNR 16             // load batch (double-buffered)

// Per-channel coefficients
__device__ float g_cr[D], g_ci[D];     // c
__device__ float g_Ar[D], g_Ai[D];     // c^LC
// Chunk end-states (zero-init local scans) and true entering prefixes
__device__ float g_er[C * BD], g_ei[C * BD];
__device__ float g_pr[C * BD], g_pi[C * BD];

// ---------------------------------------------------------------------------
// K0: per-channel coefficients in double precision.
// ---------------------------------------------------------------------------
__global__ void k0_coeffs(const float* __restrict__ lmlg,
                          const float* __restrict__ theta) {
    int d = blockIdx.x * blockDim.x + threadIdx.x;
    if (d >= D) return;
    double g  = exp(-exp((double)lmlg[d]));
    double th = (double)theta[d];
    double cr = g * cos(th);
    double ci = g * sin(th);
    g_cr[d] = (float)cr;
    g_ci[d] = (float)ci;
    double ar = cr, ai = ci;            // c^128 via 7 squarings
#pragma unroll
    for (int i = 0; i < 7; i++) {
        double nr = ar * ar - ai * ai;
        double ni = 2.0 * ar * ai;
        ar = nr; ai = ni;
    }
    g_Ar[d] = (float)ar;
    g_Ai[d] = (float)ai;
}

// ---------------------------------------------------------------------------
// K1: local scan per (chunk, channel), zero init; store end state.
// 131072 threads, 512 CTAs. Double-buffered 16-deep load pipeline.
// ---------------------------------------------------------------------------
__global__ void __launch_bounds__(256) k1_local_end(const float* __restrict__ x) {
    int tid   = blockIdx.x * blockDim.x + threadIdx.x;   // C*BD = 131072
    int chunk = tid >> 12;             // / BD
    int bd    = tid & (BD - 1);
    int d     = bd & (D - 1);
    float cr = g_cr[d], ci = g_ci[d];
    float sr = 0.f, si = 0.f;

    const float* xp = x + (size_t)chunk * LC * BD + bd;
    float xa[UNR], xb[UNR];

#pragma unroll
    for (int k = 0; k < UNR; k++)                 // prologue: batch 0
        xa[k] = __ldg(xp + (size_t)k * BD);

    for (int n = UNR; n < LC; n += UNR) {
#pragma unroll
        for (int k = 0; k < UNR; k++)             // issue next batch first
            xb[k] = __ldg(xp + (size_t)(n + k) * BD);
#pragma unroll
        for (int k = 0; k < UNR; k++) {           // consume current batch
            float nr = fmaf(cr, sr, fmaf(-ci, si, xa[k]));
            float ni = fmaf(ci, sr, cr * si);
            sr = nr; si = ni;
        }
#pragma unroll
        for (int k = 0; k < UNR; k++) xa[k] = xb[k];
    }
#pragma unroll
    for (int k = 0; k < UNR; k++) {               // epilogue
        float nr = fmaf(cr, sr, fmaf(-ci, si, xa[k]));
        float ni = fmaf(ci, sr, cr * si);
        sr = nr; si = ni;
    }
    g_er[tid] = sr;
    g_ei[tid] = si;
}

// ---------------------------------------------------------------------------
// K2: serial scan over the 32 chunk boundaries per channel.
// ---------------------------------------------------------------------------
__global__ void k2_chunk_scan(const float* __restrict__ last_conv_init) {
    int bd = blockIdx.x * blockDim.x + threadIdx.x;
    if (bd >= BD) return;
    int d = bd & (D - 1);
    float Ar = g_Ar[d], Ai = g_Ai[d];
    float sr = last_conv_init[d], si = 0.f;
    g_pr[bd] = sr; g_pi[bd] = si;
#pragma unroll
    for (int j = 0; j < C - 1; j++) {
        float e_r = g_er[j * BD + bd], e_i = g_ei[j * BD + bd];
        float nr = fmaf(Ar, sr, fmaf(-Ai, si, e_r));
        float ni = fmaf(Ai, sr, fmaf(Ar, si, e_i));
        sr = nr; si = ni;
        g_pr[(j + 1) * BD + bd] = sr;
        g_pi[(j + 1) * BD + bd] = si;
    }
}

// ---------------------------------------------------------------------------
// K3: replay seeded with true prefix; out = Re(s)*x with streaming stores.
// ---------------------------------------------------------------------------
__global__ void __launch_bounds__(256) k3_finalize(const float* __restrict__ x,
                                                   float* __restrict__ out) {
    int tid   = blockIdx.x * blockDim.x + threadIdx.x;
    int chunk = tid >> 12;
    int bd    = tid & (BD - 1);
    int d     = bd & (D - 1);
    float cr = g_cr[d], ci = g_ci[d];
    float sr = g_pr[tid], si = g_pi[tid];

    size_t base = (size_t)chunk * LC * BD + bd;
    const float* xp = x + base;
    float*       op = out + base;
    float xa[UNR], xb[UNR];

#pragma unroll
    for (int k = 0; k < UNR; k++)
        xa[k] = __ldg(xp + (size_t)k * BD);

    for (int n = UNR; n < LC; n += UNR) {
#pragma unroll
        for (int k = 0; k < UNR; k++)
            xb[k] = __ldg(xp + (size_t)(n + k) * BD);
#pragma unroll
        for (int k = 0; k < UNR; k++) {
            float nr = fmaf(cr, sr, fmaf(-ci, si, xa[k]));
            float ni = fmaf(ci, sr, cr * si);
            sr = nr; si = ni;
            __stcs(op + (size_t)(n - UNR + k) * BD, nr * xa[k]);
        }
#pragma unroll
        for (int k = 0; k < UNR; k++) xa[k] = xb[k];
    }
#pragma unroll
    for (int k = 0; k < UNR; k++) {
        float nr = fmaf(cr, sr, fmaf(-ci, si, xa[k]));
        float ni = fmaf(ci, sr, cr * si);
        sr = nr; si = ni;
        __stcs(op + (size_t)(LC - UNR + k) * BD, nr * xa[k]);
    }
}

// ---------------------------------------------------------------------------
extern "C" void kernel_launch(void* const* d_in, const int* in_sizes, int n_in,
                              void* d_out, int out_size) {
    const float* x    = (const float*)d_in[0];  // [L,B,D]
    const float* lmlg = (const float*)d_in[1];  // [D]
    const float* th   = (const float*)d_in[2];  // [D]
    const float* lci  = (const float*)d_in[3];  // [D]
    float* out = (float*)d_out;

    k0_coeffs<<<(D + 255) / 256, 256>>>(lmlg, th);
    k1_local_end<<<(C * BD) / 256, 256>>>(x);
    k2_chunk_scan<<<(BD + 255) / 256, 256>>>(lci);
    k3_finalize<<<(C * BD) / 256, 256>>>(x, out);
}